// round 16
// baseline (speedup 1.0000x reference)
#include <cuda_runtime.h>
#include <cstdint>

#define B_      2048
#define D_      512
#define NA_     512
#define CAP_    32
#define NVMAX_  8
#define WARPS_  2
#define NSL_    4
#define THR_    64
#define NCH_    32                  // k-chunks per pass (512/16)
#define SLOT4_  256                 // float4 per slot (64 rows x 16 k = 4KB)
#define RING4_  (2 * SLOT4_)        // 512 float4 per warp (2 slots)
#define SV4OFF_ (WARPS_ * RING4_)   // 1024
#define SMEMB_  ((SV4OFF_ + NVMAX_ * 128) * 16)   // 32768 B -> ~6 CTAs/SM

// ---------------- device scratch (zero-init at load; consumer-zeroed) ----
__device__ int g_counts[NSL_][NA_];
__device__ int g_buckets[NA_ * CAP_];

// ---------------- kernel 1: bucket by attribute (no zero phase) ----------
__global__ void k_bucket(const int* __restrict__ attrs) {
    int b = blockIdx.x * blockDim.x + threadIdx.x;
    if (b >= B_) return;
    int a = attrs[b];
    int pos = atomicAdd(&g_counts[0][a], 1);
    atomicAdd(&g_counts[1][a], 1);
    atomicAdd(&g_counts[2][a], 1);
    atomicAdd(&g_counts[3][a], 1);
    if (pos < CAP_) g_buckets[a * CAP_ + pos] = b;
}

// ---------------- cp.async helpers ----------------
__device__ __forceinline__ void cp16(uint32_t saddr, const void* gaddr) {
    asm volatile("cp.async.cg.shared.global [%0], [%1], 16;"
                 :: "r"(saddr), "l"(gaddr));
}
__device__ __forceinline__ void cp_commit() {
    asm volatile("cp.async.commit_group;");
}
template <int N>
__device__ __forceinline__ void cp_wait() {
    asm volatile("cp.async.wait_group %0;" :: "n"(N));
}

// stage one k-chunk (64 rows x 16 k = 4KB) into a swizzled smem slot.
// Same proven XOR pattern as the 111us kernel, extended to 64 rows
// (rows 32..63 are the identical pattern at +2KB).
__device__ __forceinline__ void issue_chunk(
    uint32_t sslot, const float4* __restrict__ gbase, int c, int lane)
{
    int sub = lane >> 2;        // 0..7 row-within-group
    int off = lane & 3;         // 0..3 float4-within-chunk-row
    const float4* g = gbase + c * 4 + off;
#pragma unroll
    for (int i = 0; i < 8; i++) {
        int row = i * 8 + sub;  // 0..63
        uint32_t a4 = (uint32_t)(row * 4 + (off ^ (row & 3)));
        cp16(sslot + a4 * 16, g + (size_t)row * 128);
    }
    cp_commit();
}

// lane owns rows (lane) and (lane+32): each broadcast v is reused by BOTH
// rows' FMAs -> vector wavefronts per matrix byte halved vs 1 row/lane.
// Both matrix LDS use the proven conflict-free XOR pattern.
template <int NV>
__device__ __forceinline__ void chunk_fma(
    const float4* __restrict__ sp, const float4* __restrict__ sv4,
    float* __restrict__ accA, float* __restrict__ accB, int c, int lane)
{
#pragma unroll
    for (int k4 = 0; k4 < 4; k4++) {
        float4 mA = sp[lane * 4 + (k4 ^ (lane & 3))];
        float4 mB = sp[128 + lane * 4 + (k4 ^ (lane & 3))];
#pragma unroll
        for (int j = 0; j < NV; j++) {
            float4 v = sv4[j * 128 + c * 4 + k4];     // broadcast, 1 wf
            accA[j] = fmaf(mA.x, v.x, accA[j]);
            accA[j] = fmaf(mA.y, v.y, accA[j]);
            accA[j] = fmaf(mA.z, v.z, accA[j]);
            accA[j] = fmaf(mA.w, v.w, accA[j]);
            accB[j] = fmaf(mB.x, v.x, accB[j]);
            accB[j] = fmaf(mB.y, v.y, accB[j]);
            accB[j] = fmaf(mB.z, v.z, accB[j]);
            accB[j] = fmaf(mB.w, v.w, accB[j]);
        }
    }
}

// ---------------- per-warp pass: 64 rows, depth-2 cp.async ring -----------
template <int NV>
__device__ __forceinline__ void run_pass(
    const float4* __restrict__ gbase,
    float4* __restrict__ slot0, float4* __restrict__ slot1,
    uint32_t s0, uint32_t s1,
    const float4* __restrict__ sv4,
    const int* __restrict__ ssamp,
    int nv, float* __restrict__ out, int grow0, int lane)
{
    float accA[NV], accB[NV];
#pragma unroll
    for (int j = 0; j < NV; j++) { accA[j] = 0.0f; accB[j] = 0.0f; }

    issue_chunk(s0, gbase, 0, lane);
    issue_chunk(s1, gbase, 1, lane);

#pragma unroll 1
    for (int c = 0; c < NCH_ - 2; c++) {
        cp_wait<1>();
        __syncwarp();
        chunk_fma<NV>((c & 1) ? slot1 : slot0, sv4, accA, accB, c, lane);
        __syncwarp();
        issue_chunk((c & 1) ? s1 : s0, gbase, c + 2, lane);
    }
    cp_wait<1>(); __syncwarp();
    chunk_fma<NV>(slot0, sv4, accA, accB, NCH_ - 2, lane);
    cp_wait<0>(); __syncwarp();
    chunk_fma<NV>(slot1, sv4, accA, accB, NCH_ - 1, lane);

    int rowA = grow0 + lane;
    int rowB = grow0 + lane + 32;
#pragma unroll
    for (int j = 0; j < NV; j++) {
        if (j < nv) {
            out[(size_t)ssamp[j] * D_ + rowA] = fmaxf(accA[j], 0.0f);
            out[(size_t)ssamp[j] * D_ + rowB] = fmaxf(accB[j], 0.0f);
        }
    }
}

// ---------------- kernel 2: per-attribute matvec ------------------------
// grid = (NA_, NSL_), 64 threads (2 warps x 64 rows = 128 rows per CTA,
// ~31us quantum preserved).
__global__ __launch_bounds__(THR_) void k_compute(
    const int*   __restrict__ attrs,
    const int*   __restrict__ objs,
    const float* __restrict__ attr_ops,
    const float* __restrict__ obj_emb,
    float*       __restrict__ out)
{
    extern __shared__ float4 smem4[];
    float4* ring = smem4;                          // [2][2][256] f4 = 16 KB
    float4* sv4  = smem4 + SV4OFF_;                // [8][128]    f4 = 16 KB
    __shared__ int ssamp[NVMAX_];

    int tid  = threadIdx.x;
    int lane = tid & 31;
    int warp = tid >> 5;
    int a    = blockIdx.x;
    int y    = blockIdx.y;

    int cnt = g_counts[y][a];

    int grow0 = y * 128 + warp * 64;
    const float4* Mw =
        (const float4*)(attr_ops + (size_t)a * D_ * D_) + (size_t)grow0 * 128;
    float4*  slot0 = ring + warp * RING4_;
    float4*  slot1 = slot0 + SLOT4_;
    uint32_t s0 = (uint32_t)__cvta_generic_to_shared(slot0);
    uint32_t s1 = (uint32_t)__cvta_generic_to_shared(slot1);

    if (cnt <= CAP_) {
        for (int base = 0; base < cnt; base += NVMAX_) {
            int nv = cnt - base;
            if (nv > NVMAX_) nv = NVMAX_;
            int NVsel = (nv <= 1) ? 1 : (nv <= 2) ? 2 : (nv <= 4) ? 4 : 8;

            __syncthreads();                  // prior pass done reading sv4
            if (tid < nv) ssamp[tid] = g_buckets[a * CAP_ + base + tid];
            __syncthreads();

            for (int u = tid; u < NVsel * 128; u += THR_) {
                int j = u >> 7;
                float4 val = make_float4(0.f, 0.f, 0.f, 0.f);
                if (j < nv)
                    val = ((const float4*)(obj_emb + (size_t)objs[ssamp[j]] * D_))[u & 127];
                sv4[u] = val;
            }
            __syncthreads();

            switch (NVsel) {
                case 1: run_pass<1>(Mw, slot0, slot1, s0, s1, sv4, ssamp, nv, out, grow0, lane); break;
                case 2: run_pass<2>(Mw, slot0, slot1, s0, s1, sv4, ssamp, nv, out, grow0, lane); break;
                case 4: run_pass<4>(Mw, slot0, slot1, s0, s1, sv4, ssamp, nv, out, grow0, lane); break;
                default: run_pass<8>(Mw, slot0, slot1, s0, s1, sv4, ssamp, nv, out, grow0, lane); break;
            }
        }
    } else {
        // overflow (cnt > CAP): uniform in-CTA scan — correctness safety net,
        // never taken for Poisson(4) buckets.
        int nb = 0;
        for (int b = 0; b < B_; b++) {
            if (attrs[b] == a) {
                __syncthreads();
                if (tid == 0) ssamp[nb] = b;
                nb++;
                if (nb == NVMAX_) {
                    __syncthreads();
                    for (int u = tid; u < NVMAX_ * 128; u += THR_) {
                        int j = u >> 7;
                        sv4[u] = ((const float4*)(obj_emb +
                                   (size_t)objs[ssamp[j]] * D_))[u & 127];
                    }
                    __syncthreads();
                    run_pass<8>(Mw, slot0, slot1, s0, s1, sv4, ssamp, NVMAX_, out, grow0, lane);
                    nb = 0;
                }
            }
        }
        if (nb > 0) {
            __syncthreads();
            for (int u = tid; u < NVMAX_ * 128; u += THR_) {
                int j = u >> 7;
                float4 val = make_float4(0.f, 0.f, 0.f, 0.f);
                if (j < nb)
                    val = ((const float4*)(obj_emb + (size_t)objs[ssamp[j]] * D_))[u & 127];
                sv4[u] = val;
            }
            __syncthreads();
            run_pass<8>(Mw, slot0, slot1, s0, s1, sv4, ssamp, nb, out, grow0, lane);
        }
    }

    // restore clean state for next graph replay (sole reader of this slot)
    if (tid == 0) g_counts[y][a] = 0;
}

// ---------------- launch -------------------------------------------------
extern "C" void kernel_launch(void* const* d_in, const int* in_sizes, int n_in,
                              void* d_out, int out_size)
{
    const int*   attrs    = (const int*)d_in[0];
    const int*   objs     = (const int*)d_in[1];
    const float* attr_ops = (const float*)d_in[2];
    const float* obj_emb  = (const float*)d_in[3];
    float*       out      = (float*)d_out;

    cudaFuncSetAttribute(k_compute,
                         cudaFuncAttributeMaxDynamicSharedMemorySize, SMEMB_);

    k_bucket<<<(B_ + 255) / 256, 256>>>(attrs);
    k_compute<<<dim3(NA_, NSL_), THR_, SMEMB_>>>(attrs, objs, attr_ops, obj_emb, out);
}

// round 17
// speedup vs baseline: 1.0876x; 1.0876x over previous
#include <cuda_runtime.h>
#include <cstdint>

#define B_      2048
#define D_      512
#define NA_     512
#define CAP_    32
#define NVMAX_  8
#define WARPS_  4
#define NSL_    4
#define THR_    128
#define NCH_    32                  // k-chunks per pass (512/16)
#define DEPTH_  4
#define SLOT4_  128                 // float4 per slot (32 rows x 16 k = 2KB)
#define RING4_  (DEPTH_ * SLOT4_)   // 512 float4 per warp
#define SV4OFF_ (WARPS_ * RING4_)   // 2048
#define SMEMB_  ((SV4OFF_ + NVMAX_ * 128) * 16)   // 49152 B -> 4 CTAs/SM

// ---------------- device scratch (zero-init at load; consumer-zeroed) ----
__device__ int g_counts[NSL_][NA_];
__device__ int g_buckets[NA_ * CAP_];

// ---------------- kernel 1: bucket by attribute (no zero phase) ----------
__global__ void k_bucket(const int* __restrict__ attrs) {
    int b = blockIdx.x * blockDim.x + threadIdx.x;
    if (b >= B_) return;
    int a = attrs[b];
    int pos = atomicAdd(&g_counts[0][a], 1);
    atomicAdd(&g_counts[1][a], 1);
    atomicAdd(&g_counts[2][a], 1);
    atomicAdd(&g_counts[3][a], 1);
    if (pos < CAP_) g_buckets[a * CAP_ + pos] = b;
}

// ---------------- cp.async helpers ----------------
__device__ __forceinline__ void cp16(uint32_t saddr, const void* gaddr) {
    asm volatile("cp.async.cg.shared.global [%0], [%1], 16;"
                 :: "r"(saddr), "l"(gaddr));
}
__device__ __forceinline__ void cp_commit() {
    asm volatile("cp.async.commit_group;");
}
template <int N>
__device__ __forceinline__ void cp_wait() {
    asm volatile("cp.async.wait_group %0;" :: "n"(N));
}

// stage one k-chunk (32 rows x 16 k = 2KB) into a swizzled smem slot.
// (verbatim from the proven 111us kernel)
__device__ __forceinline__ void issue_chunk(
    uint32_t sslot, const float4* __restrict__ gbase, int c, int lane)
{
    int sub = lane >> 2;        // 0..7 row-within-group
    int off = lane & 3;         // 0..3 float4-within-chunk-row
    const float4* g = gbase + c * 4 + off;
#pragma unroll
    for (int i = 0; i < 4; i++) {
        int row = i * 8 + sub;
        uint32_t a4 = (uint32_t)(row * 4 + (off ^ (row & 3)));
        cp16(sslot + a4 * 16, g + (size_t)row * 128);
    }
    cp_commit();
}

// reader: slot[lane*4 + (k4 ^ (lane&3))] — XOR bijective, conflict-free;
// vector read uniform across warp -> true broadcast (lane = row mapping)
template <int NV>
__device__ __forceinline__ void chunk_fma(
    const float4* __restrict__ sp, const float4* __restrict__ sv4,
    float* __restrict__ acc, int c, int lane)
{
#pragma unroll
    for (int k4 = 0; k4 < 4; k4++) {
        float4 m = sp[lane * 4 + (k4 ^ (lane & 3))];
#pragma unroll
        for (int j = 0; j < NV; j++) {
            float4 v = sv4[j * 128 + c * 4 + k4];     // broadcast, 1 wf
            acc[j] = fmaf(m.x, v.x, acc[j]);
            acc[j] = fmaf(m.y, v.y, acc[j]);
            acc[j] = fmaf(m.z, v.z, acc[j]);
            acc[j] = fmaf(m.w, v.w, acc[j]);
        }
    }
}

// ---------------- per-warp pass: depth-4 ring, issue BEFORE compute -------
// During every compute window chunks c+1, c+2, c+3 are in flight (6KB/warp,
// 3x the depth-2 scheme). Slot (c+3)&3 == (c-1)&3 was fully read at iter
// c-1 and this iter's post-wait syncwarp orders those reads before reuse.
template <int NV>
__device__ __forceinline__ void run_pass(
    const float4* __restrict__ gbase,
    float4* __restrict__ ringw, uint32_t ring_s,
    const float4* __restrict__ sv4,
    const int* __restrict__ ssamp,
    int nv, float* __restrict__ out, int grow0, int lane)
{
    float acc[NV];
#pragma unroll
    for (int j = 0; j < NV; j++) acc[j] = 0.0f;

    issue_chunk(ring_s,        gbase, 0, lane);
    issue_chunk(ring_s + 2048, gbase, 1, lane);
    issue_chunk(ring_s + 4096, gbase, 2, lane);

#pragma unroll 1
    for (int c = 0; c < NCH_ - 2; c++) {
        cp_wait<2>();                 // chunk c retired; c+1..c+2(+3) pending
        __syncwarp();                 // staged data visible; prior slot reads done
        if (c + 3 < NCH_)
            issue_chunk(ring_s + (uint32_t)((c + 3) & 3) * 2048, gbase, c + 3, lane);
        chunk_fma<NV>(ringw + (c & 3) * SLOT4_, sv4, acc, c, lane);
    }
    cp_wait<1>(); __syncwarp();
    chunk_fma<NV>(ringw + ((NCH_ - 2) & 3) * SLOT4_, sv4, acc, NCH_ - 2, lane);
    cp_wait<0>(); __syncwarp();
    chunk_fma<NV>(ringw + ((NCH_ - 1) & 3) * SLOT4_, sv4, acc, NCH_ - 1, lane);

    int row = grow0 + lane;
#pragma unroll
    for (int j = 0; j < NV; j++)
        if (j < nv)
            out[(size_t)ssamp[j] * D_ + row] = fmaxf(acc[j], 0.0f);
}

// ---------------- kernel 2: per-attribute matvec ------------------------
// grid = (NA_, NSL_), 128 threads (4 warps x 32 rows = 128 rows per CTA,
// ~31us work quantum — the R14 winner).
__global__ __launch_bounds__(THR_) void k_compute(
    const int*   __restrict__ attrs,
    const int*   __restrict__ objs,
    const float* __restrict__ attr_ops,
    const float* __restrict__ obj_emb,
    float*       __restrict__ out)
{
    extern __shared__ float4 smem4[];
    float4* ring = smem4;                          // [4][4][128] f4 = 32 KB
    float4* sv4  = smem4 + SV4OFF_;                // [8][128]    f4 = 16 KB
    __shared__ int ssamp[NVMAX_];

    int tid  = threadIdx.x;
    int lane = tid & 31;
    int warp = tid >> 5;
    int a    = blockIdx.x;
    int y    = blockIdx.y;

    int cnt = g_counts[y][a];

    int grow0 = y * (WARPS_ * 32) + warp * 32;
    const float4* Mw =
        (const float4*)(attr_ops + (size_t)a * D_ * D_) + (size_t)grow0 * 128;
    float4*  ringw  = ring + warp * RING4_;
    uint32_t ring_s = (uint32_t)__cvta_generic_to_shared(ringw);

    if (cnt <= CAP_) {
        for (int base = 0; base < cnt; base += NVMAX_) {
            int nv = cnt - base;
            if (nv > NVMAX_) nv = NVMAX_;
            int NVsel = (nv <= 1) ? 1 : (nv <= 2) ? 2 : (nv <= 4) ? 4 : 8;

            __syncthreads();                  // prior pass done reading sv4
            if (tid < nv) ssamp[tid] = g_buckets[a * CAP_ + base + tid];
            __syncthreads();

            for (int u = tid; u < NVsel * 128; u += THR_) {
                int j = u >> 7;
                float4 val = make_float4(0.f, 0.f, 0.f, 0.f);
                if (j < nv)
                    val = ((const float4*)(obj_emb + (size_t)objs[ssamp[j]] * D_))[u & 127];
                sv4[u] = val;
            }
            __syncthreads();

            switch (NVsel) {
                case 1: run_pass<1>(Mw, ringw, ring_s, sv4, ssamp, nv, out, grow0, lane); break;
                case 2: run_pass<2>(Mw, ringw, ring_s, sv4, ssamp, nv, out, grow0, lane); break;
                case 4: run_pass<4>(Mw, ringw, ring_s, sv4, ssamp, nv, out, grow0, lane); break;
                default: run_pass<8>(Mw, ringw, ring_s, sv4, ssamp, nv, out, grow0, lane); break;
            }
        }
    } else {
        // overflow (cnt > CAP): uniform in-CTA scan — correctness safety net,
        // never taken for Poisson(4) buckets.
        int nb = 0;
        for (int b = 0; b < B_; b++) {
            if (attrs[b] == a) {
                __syncthreads();
                if (tid == 0) ssamp[nb] = b;
                nb++;
                if (nb == NVMAX_) {
                    __syncthreads();
                    for (int u = tid; u < NVMAX_ * 128; u += THR_) {
                        int j = u >> 7;
                        sv4[u] = ((const float4*)(obj_emb +
                                   (size_t)objs[ssamp[j]] * D_))[u & 127];
                    }
                    __syncthreads();
                    run_pass<8>(Mw, ringw, ring_s, sv4, ssamp, NVMAX_, out, grow0, lane);
                    nb = 0;
                }
            }
        }
        if (nb > 0) {
            __syncthreads();
            for (int u = tid; u < NVMAX_ * 128; u += THR_) {
                int j = u >> 7;
                float4 val = make_float4(0.f, 0.f, 0.f, 0.f);
                if (j < nb)
                    val = ((const float4*)(obj_emb + (size_t)objs[ssamp[j]] * D_))[u & 127];
                sv4[u] = val;
            }
            __syncthreads();
            run_pass<8>(Mw, ringw, ring_s, sv4, ssamp, nb, out, grow0, lane);
        }
    }

    // restore clean state for next graph replay (sole reader of this slot)
    if (tid == 0) g_counts[y][a] = 0;
}

// ---------------- launch -------------------------------------------------
extern "C" void kernel_launch(void* const* d_in, const int* in_sizes, int n_in,
                              void* d_out, int out_size)
{
    const int*   attrs    = (const int*)d_in[0];
    const int*   objs     = (const int*)d_in[1];
    const float* attr_ops = (const float*)d_in[2];
    const float* obj_emb  = (const float*)d_in[3];
    float*       out      = (float*)d_out;

    cudaFuncSetAttribute(k_compute,
                         cudaFuncAttributeMaxDynamicSharedMemorySize, SMEMB_);

    k_bucket<<<(B_ + 255) / 256, 256>>>(attrs);
    k_compute<<<dim3(NA_, NSL_), THR_, SMEMB_>>>(attrs, objs, attr_ops, obj_emb, out);
}